// round 4
// baseline (speedup 1.0000x reference)
#include <cuda_runtime.h>
#include <stdint.h>

// Problem constants
#define BB 16
#define CC 4
#define HH 512
#define WW 1024
#define ROWS (BB * CC * HH)       // 32768
#define NBLK (ROWS / 8)           // 4096 blocks, 8 rows each
#define BCN  (BB * CC)            // 64 (b,c) groups; 64 block-partials per group

// Scratch: per-block partial (err_sum, cnt_sum) — 32 KB static device memory.
__device__ float2 g_part[NBLK];
// Completion counter for last-block reduction (reset by last block each launch).
__device__ unsigned int g_count = 0;

// ---------------------------------------------------------------------------
// Fused kernel: one warp per row.
//  Phase A (all blocks): argmax over W=1024 of cls_true (first-max semantics),
//    gather offset_pred/offset_true at that index, apply vertical mask,
//    block-reduce the 8 rows into one float2 partial, bump the counter.
//  Phase B (last block only): reduce the 4096 partials per (b,c) group,
//    compute per-group means, sum, write the scalar. Fixed order -> bitwise
//    deterministic across runs/replays.
// ---------------------------------------------------------------------------
__global__ __launch_bounds__(256) void offset_loss_kernel(
    const float* __restrict__ offset_pred,
    const float* __restrict__ offset_true,
    const float* __restrict__ cls_true,
    const float* __restrict__ vertical_true,
    float* __restrict__ out)
{
    const int warp_in_block = threadIdx.x >> 5;
    const int lane = threadIdx.x & 31;
    const int row = blockIdx.x * 8 + warp_in_block;

    const float4* crow = reinterpret_cast<const float4*>(cls_true + (size_t)row * WW);

    // Front-batch all 8 coalesced float4 loads (512B/warp each) -> MLP 8.
    float4 v[8];
#pragma unroll
    for (int k = 0; k < 8; k++) {
        v[k] = __ldcs(&crow[k * 32 + lane]);   // streaming: read-once data
    }

    // Per-lane scan in increasing index order (first-max within lane).
    float best = -__int_as_float(0x7f800000);  // -inf
    int   bidx = 0;
#pragma unroll
    for (int k = 0; k < 8; k++) {
        const int base = (k * 32 + lane) * 4;
        if (v[k].x > best) { best = v[k].x; bidx = base + 0; }
        if (v[k].y > best) { best = v[k].y; bidx = base + 1; }
        if (v[k].z > best) { best = v[k].z; bidx = base + 2; }
        if (v[k].w > best) { best = v[k].w; bidx = base + 3; }
    }

    // Warp reduction: larger value wins; exact tie -> smaller index (first-max).
#pragma unroll
    for (int off = 16; off > 0; off >>= 1) {
        float oval = __shfl_xor_sync(0xffffffffu, best, off);
        int   oidx = __shfl_xor_sync(0xffffffffu, bidx, off);
        if (oval > best || (oval == best && oidx < bidx)) {
            best = oval;
            bidx = oidx;
        }
    }

    // Lane 0 of each warp: gather + mask for this row.
    __shared__ float s_err[8];
    __shared__ float s_cnt[8];
    __shared__ bool  s_last;
    if (lane == 0) {
        const size_t gidx = (size_t)row * WW + bidx;
        float p = __ldg(&offset_pred[gidx]);
        float t = __ldg(&offset_true[gidx]);
        float mask = (__ldg(&vertical_true[row]) >= 0.5f) ? 1.0f : 0.0f;
        s_err[warp_in_block] = fabsf(p - t) * mask;
        s_cnt[warp_in_block] = mask;
    }
    __syncthreads();

    // Warp 0, lanes 0..7 hold the 8 row results -> reduce; thread 0 publishes
    // the partial and bumps the completion counter.
    if (threadIdx.x < 8) {
        float e = s_err[threadIdx.x];
        float c = s_cnt[threadIdx.x];
#pragma unroll
        for (int off = 4; off > 0; off >>= 1) {
            e += __shfl_xor_sync(0x000000ffu, e, off);
            c += __shfl_xor_sync(0x000000ffu, c, off);
        }
        if (threadIdx.x == 0) {
            g_part[blockIdx.x] = make_float2(e, c);
            __threadfence();
            unsigned prev = atomicAdd(&g_count, 1u);
            s_last = (prev == (unsigned)(NBLK - 1));
            if (s_last) g_count = 0;   // reset for next graph replay
        }
    }
    __syncthreads();
    if (!s_last) return;

    // ---- Phase B: last block reduces all partials (32 KB, L2-hot) ----
    __threadfence();  // acquire side: ensure g_part writes are visible

    const int t   = threadIdx.x;
    const int bc  = t >> 2;   // 0..63 : one (b,c) group per 4 threads
    const int sub = t & 3;

    float err = 0.0f;
    float cnt = 0.0f;
#pragma unroll
    for (int j = 0; j < 16; j++) {
        float2 p = g_part[bc * 64 + j * 4 + sub];
        err += p.x;
        cnt += p.y;
    }
    // Reduce within each 4-lane group (bc is 4-lane aligned, xor 1/2 stays inside).
#pragma unroll
    for (int off = 1; off < 4; off <<= 1) {
        err += __shfl_xor_sync(0xffffffffu, err, off);
        cnt += __shfl_xor_sync(0xffffffffu, cnt, off);
    }

    __shared__ float s_pbc[BCN];
    if (sub == 0) {
        s_pbc[bc] = (cnt > 0.0f) ? (err / fmaxf(cnt, 1.0f)) : 0.0f;
    }
    __syncthreads();

    if (t < 32) {
        float vsum = s_pbc[t] + s_pbc[t + 32];
#pragma unroll
        for (int off = 16; off > 0; off >>= 1) {
            vsum += __shfl_xor_sync(0xffffffffu, vsum, off);
        }
        if (t == 0) {
            out[0] = vsum / (float)BB;
        }
    }
}

// ---------------------------------------------------------------------------
extern "C" void kernel_launch(void* const* d_in, const int* in_sizes, int n_in,
                              void* d_out, int out_size)
{
    const float* offset_pred   = (const float*)d_in[0];
    const float* offset_true   = (const float*)d_in[1];
    const float* cls_true      = (const float*)d_in[2];
    const float* vertical_true = (const float*)d_in[3];
    float* out = (float*)d_out;

    offset_loss_kernel<<<NBLK, 256>>>(offset_pred, offset_true, cls_true,
                                      vertical_true, out);
}

// round 5
// speedup vs baseline: 1.0865x; 1.0865x over previous
#include <cuda_runtime.h>
#include <stdint.h>

// Problem constants
#define BB 16
#define CC 4
#define HH 512
#define WW 1024
#define ROWS (BB * CC * HH)       // 32768
#define NBLK (ROWS / 8)           // 4096 blocks, 8 rows each
#define BCN  (BB * CC)            // 64 (b,c) groups; 64 block-partials per group

// Scratch: per-block partial (err_sum, cnt_sum) — 32 KB static device memory.
__device__ float2 g_part[NBLK];

// ---------------------------------------------------------------------------
// Kernel 1: one warp per row. Argmax over W=1024 of cls_true (first-max
// semantics), gather offset_pred/offset_true at that index, apply vertical
// mask, block-reduce the 8 rows into one float2 partial. No fences, no
// atomics — pure streaming at the HBM roofline.
// ---------------------------------------------------------------------------
__global__ __launch_bounds__(256) void row_argmax_kernel(
    const float* __restrict__ offset_pred,
    const float* __restrict__ offset_true,
    const float* __restrict__ cls_true,
    const float* __restrict__ vertical_true)
{
    const int warp_in_block = threadIdx.x >> 5;
    const int lane = threadIdx.x & 31;
    const int row = blockIdx.x * 8 + warp_in_block;

    const float4* crow = reinterpret_cast<const float4*>(cls_true + (size_t)row * WW);

    // Front-batch all 8 coalesced float4 loads (512B/warp each) -> MLP 8.
    float4 v[8];
#pragma unroll
    for (int k = 0; k < 8; k++) {
        v[k] = __ldcs(&crow[k * 32 + lane]);   // streaming: read-once data
    }

    // Per-lane scan in increasing index order (first-max within lane).
    float best = -__int_as_float(0x7f800000);  // -inf
    int   bidx = 0;
#pragma unroll
    for (int k = 0; k < 8; k++) {
        const int base = (k * 32 + lane) * 4;
        if (v[k].x > best) { best = v[k].x; bidx = base + 0; }
        if (v[k].y > best) { best = v[k].y; bidx = base + 1; }
        if (v[k].z > best) { best = v[k].z; bidx = base + 2; }
        if (v[k].w > best) { best = v[k].w; bidx = base + 3; }
    }

    // Warp reduction: larger value wins; exact tie -> smaller index (first-max).
#pragma unroll
    for (int off = 16; off > 0; off >>= 1) {
        float oval = __shfl_xor_sync(0xffffffffu, best, off);
        int   oidx = __shfl_xor_sync(0xffffffffu, bidx, off);
        if (oval > best || (oval == best && oidx < bidx)) {
            best = oval;
            bidx = oidx;
        }
    }

    // Lane 0 of each warp: gather + mask for this row.
    __shared__ float s_err[8];
    __shared__ float s_cnt[8];
    if (lane == 0) {
        const size_t gidx = (size_t)row * WW + bidx;
        float p = __ldg(&offset_pred[gidx]);
        float t = __ldg(&offset_true[gidx]);
        float mask = (__ldg(&vertical_true[row]) >= 0.5f) ? 1.0f : 0.0f;
        s_err[warp_in_block] = fabsf(p - t) * mask;
        s_cnt[warp_in_block] = mask;
    }
    __syncthreads();

    // Warp 0, lanes 0..7 hold the 8 row results -> reduce and store partial.
    if (threadIdx.x < 8) {
        float e = s_err[threadIdx.x];
        float c = s_cnt[threadIdx.x];
#pragma unroll
        for (int off = 4; off > 0; off >>= 1) {
            e += __shfl_xor_sync(0x000000ffu, e, off);
            c += __shfl_xor_sync(0x000000ffu, c, off);
        }
        if (threadIdx.x == 0) {
            g_part[blockIdx.x] = make_float2(e, c);
        }
    }
}

// ---------------------------------------------------------------------------
// Kernel 2 (finisher, PDL secondary): ONE block, 1024 threads. Launched with
// programmatic stream serialization so its launch overhead overlaps the
// primary's execution; cudaGridDependencySynchronize() waits for the primary
// to finish before reading the (L2-hot) 32 KB of partials.
// ---------------------------------------------------------------------------
__global__ __launch_bounds__(1024) void final_reduce_kernel(float* __restrict__ out)
{
#if __CUDA_ARCH__ >= 900
    cudaGridDependencySynchronize();
#endif

    const int t    = threadIdx.x;
    const int warp = t >> 5;           // 0..31
    const int lane = t & 31;

    float acc = 0.0f;                  // sum of per_bc for this warp's 2 groups

#pragma unroll
    for (int g = 0; g < 2; g++) {
        const int bc = warp * 2 + g;   // 0..63
        float err = 0.0f;
        float cnt = 0.0f;
#pragma unroll
        for (int j = 0; j < 2; j++) {
            float2 p = g_part[bc * 64 + j * 32 + lane];
            err += p.x;
            cnt += p.y;
        }
#pragma unroll
        for (int off = 16; off > 0; off >>= 1) {
            err += __shfl_xor_sync(0xffffffffu, err, off);
            cnt += __shfl_xor_sync(0xffffffffu, cnt, off);
        }
        if (lane == 0) {
            acc += (cnt > 0.0f) ? (err / fmaxf(cnt, 1.0f)) : 0.0f;
        }
    }

    __shared__ float s_acc[32];
    if (lane == 0) s_acc[warp] = acc;
    __syncthreads();

    if (warp == 0) {
        float vsum = s_acc[lane];
#pragma unroll
        for (int off = 16; off > 0; off >>= 1) {
            vsum += __shfl_xor_sync(0xffffffffu, vsum, off);
        }
        if (lane == 0) {
            out[0] = vsum / (float)BB;
        }
    }
}

// ---------------------------------------------------------------------------
extern "C" void kernel_launch(void* const* d_in, const int* in_sizes, int n_in,
                              void* d_out, int out_size)
{
    const float* offset_pred   = (const float*)d_in[0];
    const float* offset_true   = (const float*)d_in[1];
    const float* cls_true      = (const float*)d_in[2];
    const float* vertical_true = (const float*)d_in[3];
    float* out = (float*)d_out;

    row_argmax_kernel<<<NBLK, 256>>>(offset_pred, offset_true, cls_true,
                                     vertical_true);

    // PDL launch of the finisher: overlaps its launch latency with the
    // primary kernel; the device-side gridDependencySynchronize provides the
    // ordering.
    cudaLaunchAttribute attrs[1];
    attrs[0].id = cudaLaunchAttributeProgrammaticStreamSerialization;
    attrs[0].val.programmaticStreamSerializationAllowed = 1;

    cudaLaunchConfig_t cfg = {};
    cfg.gridDim = dim3(1, 1, 1);
    cfg.blockDim = dim3(1024, 1, 1);
    cfg.dynamicSmemBytes = 0;
    cfg.stream = 0;
    cfg.attrs = attrs;
    cfg.numAttrs = 1;

    cudaLaunchKernelEx(&cfg, final_reduce_kernel, out);
}